// round 9
// baseline (speedup 1.0000x reference)
#include <cuda_runtime.h>

// GraphDenoiser N=768, F=256, H=128 — 7 launches, full-K small GEMMs,
// f32x2-packed GEMM inner loops, fused slab-reduce loads.

#define NN   768
#define FDIM 256
#define HH   128
#define MN   (NN * HH)       // 98304
#define MN2  (NN * 2 * HH)   // 196608

typedef unsigned long long ull;

// ------------------- scratch -------------------
__device__ __align__(16) float g_dinv[NN];
__device__ __align__(16) float g_bpack[HH * 2 * HH];
__device__ __align__(16) float g_c[HH];
__device__ __align__(16) float g_xwf[MN];       // hwf
__device__ __align__(16) float g_pqf[MN2];
__device__ __align__(16) float g_sig[NN * NN];
__device__ __align__(16) float g_S1[12 * MN];   // adj-gemm slabs
__device__ __align__(16) float g_S2[2 * MN];    // xw k-slabs

// ------------------- f32x2 helpers -------------------
__device__ __forceinline__ ull pk2(float lo, float hi) {
    ull d;
    asm("mov.b64 %0, {%1, %2};" : "=l"(d) : "f"(lo), "f"(hi));
    return d;
}
__device__ __forceinline__ float2 upk2(ull d) {
    float2 v;
    asm("mov.b64 {%0, %1}, %2;" : "=f"(v.x), "=f"(v.y) : "l"(d));
    return v;
}
#define F32X2_ADD(d, a, b) \
    asm("add.rn.f32x2 %0, %1, %2;" : "=l"(d) : "l"(a), "l"(b))
#define F32X2_FMA(d, a, b, c) \
    asm("fma.rn.f32x2 %0, %1, %2, %3;" : "=l"(d) : "l"(a), "l"(b), "l"(c))

// ------------------- small GEMM: 16 rows x 128 cols, BK=16, double-buffered --
// AMODE: 0 plain | 2 relu(dinv[row] * sum SA slabs)
template<int AMODE, int SA>
__device__ __forceinline__ void gemm16(
    const float* __restrict__ A, const float* __restrict__ B,
    float* __restrict__ out, float* sm,
    int row0, int bcol0, int ocol0, int kb, int nsteps,
    int lda, int ldb, int ldo, bool addc)
{
    float* smA = sm;               // [2][16][17]  As[buf][k][row]
    float* smB = sm + 2 * 16 * 17; // [2][16][132]
    const int tid = threadIdx.x;
    const int ty = tid >> 5;                 // 0..15 output row
    const int tx = tid & 31;                 // cols tx*4
    const int arow = tid >> 4, akk = tid & 15;   // A loader (tid<256), coalesced in k
    const int br = tid >> 5, bc4 = (tid & 31) * 4;

    auto ldA = [&](int k0) -> float {
        int gr = row0 + arow, gk = k0 + akk;
        if (AMODE == 2) {
            float v = 0.f;
            const float* base = A + gr * lda + gk;
            #pragma unroll
            for (int s = 0; s < SA; s++) v += base[s * MN];
            return fmaxf(v * g_dinv[gr], 0.f);
        }
        return A[gr * lda + gk];
    };
    auto ldB = [&](int k0) -> float4 {
        return *(const float4*)&B[(k0 + br) * ldb + bcol0 + bc4];
    };

    float a_reg = 0.f;
    if (tid < 256) a_reg = ldA(kb);
    float4 b_reg = ldB(kb);
    int buf = 0;
    if (tid < 256) smA[akk * 17 + arow] = a_reg;
    *(float4*)&smB[br * 132 + bc4] = b_reg;
    __syncthreads();

    ull acc2[2] = {0ull, 0ull};
    for (int s = 0; s < nsteps; s++) {
        bool more = (s + 1 < nsteps);
        float a_n = 0.f; float4 b_n;
        if (more) {
            if (tid < 256) a_n = ldA(kb + (s + 1) * 16);
            b_n = ldB(kb + (s + 1) * 16);
        }
        const float* cA = smA + buf * 16 * 17;
        const float* cB = smB + buf * 16 * 132;
        #pragma unroll
        for (int k = 0; k < 16; k++) {
            float a = cA[k * 17 + ty];
            float4 b4 = *(const float4*)&cB[k * 132 + tx * 4];
            ull b01 = pk2(b4.x, b4.y);
            ull b23 = pk2(b4.z, b4.w);
            ull ad = pk2(a, a);
            F32X2_FMA(acc2[0], ad, b01, acc2[0]);
            F32X2_FMA(acc2[1], ad, b23, acc2[1]);
        }
        if (more) {
            buf ^= 1;
            float* nA = smA + buf * 16 * 17;
            float* nB = smB + buf * 16 * 132;
            if (tid < 256) nA[akk * 17 + arow] = a_n;
            *(float4*)&nB[br * 132 + bc4] = b_n;
            __syncthreads();
        }
    }
    float2 u0 = upk2(acc2[0]), u1 = upk2(acc2[1]);
    float4 res = make_float4(u0.x, u0.y, u1.x, u1.y);
    if (addc) {
        float4 c = *(const float4*)&g_c[tx * 4];   // ocol0==HH when addc
        res.x += c.x; res.y += c.y; res.z += c.z; res.w += c.w;
    }
    *(float4*)&out[(row0 + ty) * ldo + ocol0 + tx * 4] = res;
}

// ------------------- K1: prelude + xw (full K, 2 k-slabs) -------------------
__global__ void __launch_bounds__(512)
k_pre(const float* __restrict__ x, const float* __restrict__ w1,
      const float* __restrict__ adj, const float* __restrict__ time_emb,
      const int* __restrict__ t_ptr, const float* __restrict__ we1,
      const float* __restrict__ be1)
{
    __shared__ __align__(16) float sm[4768];
    const int b = blockIdx.x;
    const int tid = threadIdx.x;
    if (b < 96) {
        int rowtile = b % 48, z = b / 48;       // z slab over k halves of 256
        gemm16<0, 1>(x, w1, g_S2 + z * MN, sm,
                     rowtile * 16, 0, 0, z * 128, 8, FDIM, HH, HH, false);
    } else {
        int rb = b - 96;                        // 0..47
        {   // dinv: 16 warps/block x 48 blocks = 768 rows
            int row  = rb * 16 + (tid >> 5);
            int lane = tid & 31;
            const float4* r = (const float4*)(adj + row * NN);
            float s = 0.f;
            #pragma unroll
            for (int j = lane; j < NN / 4; j += 32) {
                float4 v = r[j];
                s += (v.x + v.y) + (v.z + v.w);
            }
            #pragma unroll
            for (int o = 16; o; o >>= 1) s += __shfl_xor_sync(0xffffffffu, s, o);
            s += 1.0f;
            if (lane == 0) g_dinv[row] = (s > 0.f) ? rsqrtf(s) : 0.f;
        }
        for (int idx = rb * 512 + tid; idx < HH * 2 * HH; idx += 48 * 512) {
            int k = idx >> 8, n = idx & 255;
            g_bpack[idx] = (n < HH) ? we1[k * HH + n] : we1[(HH + k) * HH + (n - HH)];
        }
        if (rb == 47 && tid < HH) {
            int t = t_ptr[0];
            const float* te = time_emb + t * HH;
            float s = be1[tid];
            #pragma unroll 8
            for (int k = 0; k < HH; k++)
                s = fmaf(te[k], we1[(2 * HH + k) * HH + tid], s);
            g_c[tid] = s;
        }
    }
}

// ------------------- adj GEMM: (adj+I) @ [dinv_k * sum SB slabs(B)] ----------
// 64x128 tile, split z=12 (kchunk 64, nsteps=4), f32x2 inner.
template<int SB>
__global__ void __launch_bounds__(512)
k_adj(const float* __restrict__ adj, const float* __restrict__ Bsrc) {
    __shared__ __align__(16) float sm[2 * 16 * 68 + 2 * 16 * 132];
    float* smA = sm;
    float* smB = sm + 2 * 16 * 68;
    const int row0 = (blockIdx.x % 12) * 64;
    const int z    = blockIdx.x / 12;
    const int kb   = z * 64;
    const int tid  = threadIdx.x;
    const int ty = tid >> 5, tx = tid & 31;
    const int ar = tid >> 3, ac2 = (tid & 7) * 2;
    const int br = tid >> 5, bc4 = (tid & 31) * 4;
    const int gr = row0 + ar;

    auto ldA = [&](int k0) -> float2 {
        int gk = k0 + ac2;
        float2 v = *(const float2*)&adj[gr * NN + gk];
        if (gr == gk)          v.x += 1.0f;
        else if (gr == gk + 1) v.y += 1.0f;
        return v;
    };
    auto ldB = [&](int k0) -> float4 {
        int gk = k0 + br;
        float4 v = make_float4(0.f, 0.f, 0.f, 0.f);
        const float* base = Bsrc + gk * HH + bc4;
        #pragma unroll
        for (int s = 0; s < SB; s++) {
            float4 u = *(const float4*)(base + s * MN);
            v.x += u.x; v.y += u.y; v.z += u.z; v.w += u.w;
        }
        float sc = g_dinv[gk];
        v.x *= sc; v.y *= sc; v.z *= sc; v.w *= sc;
        return v;
    };

    ull acc2[4][2] = {};
    float2 a_reg = ldA(kb);
    float4 b_reg = ldB(kb);
    int buf = 0;
    smA[(ac2 + 0) * 68 + ar] = a_reg.x;
    smA[(ac2 + 1) * 68 + ar] = a_reg.y;
    *(float4*)&smB[br * 132 + bc4] = b_reg;
    __syncthreads();

    for (int s = 0; s < 4; s++) {
        bool more = (s + 1 < 4);
        float2 a_n; float4 b_n;
        if (more) {
            a_n = ldA(kb + (s + 1) * 16);
            b_n = ldB(kb + (s + 1) * 16);
        }
        const float* cA = smA + buf * 16 * 68;
        const float* cB = smB + buf * 16 * 132;
        #pragma unroll
        for (int k = 0; k < 16; k++) {
            float4 a4 = *(const float4*)&cA[k * 68 + ty * 4];
            float4 b4 = *(const float4*)&cB[k * 132 + tx * 4];
            ull b01 = pk2(b4.x, b4.y);
            ull b23 = pk2(b4.z, b4.w);
            float aa[4] = {a4.x, a4.y, a4.z, a4.w};
            #pragma unroll
            for (int m = 0; m < 4; m++) {
                ull ad = pk2(aa[m], aa[m]);
                F32X2_FMA(acc2[m][0], ad, b01, acc2[m][0]);
                F32X2_FMA(acc2[m][1], ad, b23, acc2[m][1]);
            }
        }
        if (more) {
            buf ^= 1;
            float* nA = smA + buf * 16 * 68;
            float* nB = smB + buf * 16 * 132;
            nA[(ac2 + 0) * 68 + ar] = a_n.x;
            nA[(ac2 + 1) * 68 + ar] = a_n.y;
            *(float4*)&nB[br * 132 + bc4] = b_n;
            __syncthreads();
        }
    }
    float* dst = g_S1 + (size_t)z * MN;
    #pragma unroll
    for (int m = 0; m < 4; m++) {
        float2 u0 = upk2(acc2[m][0]), u1 = upk2(acc2[m][1]);
        *(float4*)&dst[(row0 + ty * 4 + m) * HH + tx * 4] =
            make_float4(u0.x, u0.y, u1.x, u1.y);
    }
}

// ------------------- hw = relu(dinv*sum12 S1) @ w2 -> hwf -------------------
__global__ void __launch_bounds__(512)
k_hw(const float* __restrict__ w2) {
    __shared__ __align__(16) float sm[4768];
    gemm16<2, 12>(g_S1, w2, g_xwf, sm,
                  blockIdx.x * 16, 0, 0, 0, 8, HH, HH, HH, false);
}

// ------------------- pq = relu(dinv*sum12 S1) @ bpack (+c on q half) --------
__global__ void __launch_bounds__(512)
k_pq() {
    __shared__ __align__(16) float sm[4768];
    int rowtile = blockIdx.x % 48, col = blockIdx.x / 48;
    gemm16<2, 12>(g_S1, g_bpack, g_pqf, sm,
                  rowtile * 16, col * 128, col * 128, 0, 8, HH, 2 * HH, 2 * HH,
                  col == 1);
}

// ------------------- edge MLP + sigmoid (f32x2 packed rows) -------------------
__global__ void __launch_bounds__(512)
k_edge(const float* __restrict__ we2, const float* __restrict__ be2) {
    __shared__ __align__(16) float Ps[32 * 68];
    __shared__ __align__(8)  float Qs[32 * 66];
    __shared__ float Ws[HH];
    const int i0 = (blockIdx.x / 12) * 64;
    const int j0 = (blockIdx.x % 12) * 64;
    const int tid = threadIdx.x;
    const int ty = tid >> 5, tx = tid & 31;
    const int lr = tid >> 3, lc4 = (tid & 7) * 4;
    if (tid < HH) Ws[tid] = we2[tid];

    ull acc2[2][2] = {};
    #pragma unroll
    for (int h0 = 0; h0 < HH; h0 += 32) {
        __syncthreads();
        float4 pv = *(const float4*)&g_pqf[(i0 + lr) * 256 + h0 + lc4];
        float4 qv = *(const float4*)&g_pqf[(j0 + lr) * 256 + HH + h0 + lc4];
        Ps[(lc4 + 0) * 68 + lr] = pv.x;
        Ps[(lc4 + 1) * 68 + lr] = pv.y;
        Ps[(lc4 + 2) * 68 + lr] = pv.z;
        Ps[(lc4 + 3) * 68 + lr] = pv.w;
        Qs[(lc4 + 0) * 66 + lr] = qv.x;
        Qs[(lc4 + 1) * 66 + lr] = qv.y;
        Qs[(lc4 + 2) * 66 + lr] = qv.z;
        Qs[(lc4 + 3) * 66 + lr] = qv.w;
        __syncthreads();
        #pragma unroll
        for (int k = 0; k < 32; k++) {
            float w = Ws[h0 + k];
            ull w2 = pk2(w, w);
            float4 p4 = *(const float4*)&Ps[k * 68 + ty * 4];
            float2 q2 = *(const float2*)&Qs[k * 66 + tx * 2];
            ull pp[2] = { pk2(p4.x, p4.y), pk2(p4.z, p4.w) };
            ull qd[2] = { pk2(q2.x, q2.x), pk2(q2.y, q2.y) };
            #pragma unroll
            for (int mp = 0; mp < 2; mp++) {
                #pragma unroll
                for (int n = 0; n < 2; n++) {
                    ull sum;
                    F32X2_ADD(sum, pp[mp], qd[n]);
                    float2 sv = upk2(sum);
                    sv.x = fmaxf(sv.x, 0.f);
                    sv.y = fmaxf(sv.y, 0.f);
                    ull rv = pk2(sv.x, sv.y);
                    F32X2_FMA(acc2[mp][n], rv, w2, acc2[mp][n]);
                }
            }
        }
    }
    float bb = be2[0];
    #pragma unroll
    for (int mp = 0; mp < 2; mp++) {
        float2 c0 = upk2(acc2[mp][0]);
        float2 c1 = upk2(acc2[mp][1]);
        float2 o0, o1;
        o0.x = 1.0f / (1.0f + __expf(-(c0.x + bb)));
        o0.y = 1.0f / (1.0f + __expf(-(c1.x + bb)));
        o1.x = 1.0f / (1.0f + __expf(-(c0.y + bb)));
        o1.y = 1.0f / (1.0f + __expf(-(c1.y + bb)));
        *(float2*)&g_sig[(i0 + ty * 4 + mp * 2 + 0) * NN + j0 + tx * 2] = o0;
        *(float2*)&g_sig[(i0 + ty * 4 + mp * 2 + 1) * NN + j0 + tx * 2] = o1;
    }
}

// ------------------- symmetrize -------------------
__global__ void __launch_bounds__(512)
k_sym(float* __restrict__ out) {
    __shared__ __align__(16) float T[64 * 65];
    const int r0 = (blockIdx.x / 12) * 64;
    const int c0 = (blockIdx.x % 12) * 64;
    const int tid = threadIdx.x;
    int row = tid >> 3, c8 = (tid & 7) * 8;
    float4 v0 = *(const float4*)&g_sig[(c0 + row) * NN + r0 + c8];
    float4 v1 = *(const float4*)&g_sig[(c0 + row) * NN + r0 + c8 + 4];
    T[row * 65 + c8 + 0] = v0.x; T[row * 65 + c8 + 1] = v0.y;
    T[row * 65 + c8 + 2] = v0.z; T[row * 65 + c8 + 3] = v0.w;
    T[row * 65 + c8 + 4] = v1.x; T[row * 65 + c8 + 5] = v1.y;
    T[row * 65 + c8 + 6] = v1.z; T[row * 65 + c8 + 7] = v1.w;
    __syncthreads();
    float4 a0 = *(const float4*)&g_sig[(r0 + row) * NN + c0 + c8];
    float4 a1 = *(const float4*)&g_sig[(r0 + row) * NN + c0 + c8 + 4];
    float o[8] = {a0.x, a0.y, a0.z, a0.w, a1.x, a1.y, a1.z, a1.w};
    #pragma unroll
    for (int i = 0; i < 8; i++)
        o[i] = 0.5f * (o[i] + T[(c8 + i) * 65 + row]);
    *(float4*)&out[(r0 + row) * NN + c0 + c8]     = make_float4(o[0], o[1], o[2], o[3]);
    *(float4*)&out[(r0 + row) * NN + c0 + c8 + 4] = make_float4(o[4], o[5], o[6], o[7]);
}

// ------------------- launch -------------------
extern "C" void kernel_launch(void* const* d_in, const int* in_sizes, int n_in,
                              void* d_out, int out_size) {
    const float* x        = (const float*)d_in[0];
    const float* adj      = (const float*)d_in[1];
    const float* w1       = (const float*)d_in[2];
    const float* w2       = (const float*)d_in[3];
    const float* time_emb = (const float*)d_in[4];
    const float* we1      = (const float*)d_in[5];
    const float* be1      = (const float*)d_in[6];
    const float* we2      = (const float*)d_in[7];
    const float* be2      = (const float*)d_in[8];
    const int*   t_ptr    = (const int*)d_in[9];
    float* out = (float*)d_out;

    float *S2, *xwf;
    cudaGetSymbolAddress((void**)&S2,  g_S2);
    cudaGetSymbolAddress((void**)&xwf, g_xwf);

    k_pre<<<144, 512>>>(x, w1, adj, time_emb, t_ptr, we1, be1);
    k_adj<2><<<144, 512>>>(adj, S2);     // S1 = (adj+I) @ (dinv*(s0+s1))  [12 slabs]
    k_hw<<<48, 512>>>(w2);               // hwf = relu(dinv*sum12 S1) @ w2
    k_adj<1><<<144, 512>>>(adj, xwf);    // S1 = (adj+I) @ (dinv*hwf)      [12 slabs]
    k_pq<<<96, 512>>>();                 // pqf = relu(dinv*sum12 S1) @ bpack (+c)
    k_edge<<<144, 512>>>(we2, be2);      // sig
    k_sym<<<144, 512>>>(out);            // out = (sig+sig^T)/2
}